// round 1
// baseline (speedup 1.0000x reference)
#include <cuda_runtime.h>
#include <math.h>

#define NN     20000
#define TT     32
#define INP    64
#define HH     128
#define G3     384
#define SS     64
#define EINTRA 640000
#define EINTER 4096

// ---------------- scratch (static device globals; no allocs) ----------------
__device__ __align__(128) float    g_gi[(size_t)NN*TT*G3];   // 983 MB, reused by both layers
__device__ __align__(128) float    g_out0[(size_t)NN*TT*HH]; // 328 MB layer0 outputs
__device__ __align__(128) float    g_gh[(size_t)NN*G3];
__device__ __align__(128) float    g_h0[(size_t)NN*HH];
__device__ __align__(128) float    g_h1[(size_t)NN*HH];
__device__ __align__(128) float    g_hlin[(size_t)NN*HH];
__device__ __align__(128) float    g_acc[(size_t)NN*HH];     // intra_emb
__device__ __align__(128) float    g_Bt_ih0[INP*G3];
__device__ __align__(128) float    g_Bt_hh0[HH*G3];
__device__ __align__(128) float    g_Bt_ih1[HH*G3];
__device__ __align__(128) float    g_Bt_hh1[HH*G3];
__device__ __align__(128) float    g_Bt_intra[HH*HH];
__device__ __align__(128) float    g_Bt_inter[HH*HH];
__device__ float    g_es[NN];
__device__ float    g_ed[NN];
__device__ float    g_m[NN];
__device__ float    g_den[NN];
__device__ unsigned g_mu[NN];
__device__ float    g_eedge[EINTRA];
__device__ unsigned g_pu[SS*HH];
__device__ __align__(128) float g_pool[SS*HH];
__device__ __align__(128) float g_shlin[SS*HH];
__device__ __align__(128) float g_sacc[SS*HH];               // inter_sec

// ---------------- helpers ----------------
__device__ __forceinline__ unsigned fkey(float f) {
    unsigned u = __float_as_uint(f);
    return (u & 0x80000000u) ? ~u : (u | 0x80000000u);
}
__device__ __forceinline__ float funkey(unsigned k) {
    return (k & 0x80000000u) ? __uint_as_float(k & 0x7fffffffu)
                             : __uint_as_float(~k);
}
__device__ __forceinline__ float lrelu(float x) { return x > 0.f ? x : 0.2f * x; }

// ---------------- misc kernels ----------------
__global__ void zerof_k(float* p, int n) {
    int i = blockIdx.x * blockDim.x + threadIdx.x;
    if (i < n) p[i] = 0.f;
}
__global__ void zerou_k(unsigned* p, int n) {
    int i = blockIdx.x * blockDim.x + threadIdx.x;
    if (i < n) p[i] = 0u;
}
// W: [nrows, ncols] row-major -> Bt: [ncols, nrows] row-major (Bt[k][j] = W[j][k])
__global__ void transpose_k(const float* __restrict__ W, float* __restrict__ Bt,
                            int nrows, int ncols) {
    int idx = blockIdx.x * blockDim.x + threadIdx.x;
    if (idx >= nrows * ncols) return;
    int j = idx / ncols;
    int k = idx % ncols;
    Bt[k * nrows + j] = W[idx];
}

// ---------------- SGEMM: C[M,Nc] = A[M,K] @ Bt[K,Nc] ----------------
// A row-major (lda=K), Bt row-major (ldb=Nc). BM=BN=128, BK=16, TM=TN=8, 256 thr.
__global__ void __launch_bounds__(256) sgemm_k(const float* __restrict__ A,
                                               const float* __restrict__ Bt,
                                               float* __restrict__ C,
                                               int M, int Nc, int K) {
    __shared__ float As[16][128 + 4];
    __shared__ float Bs[16][128];
    const int tid = threadIdx.x;
    const int bm = blockIdx.x * 128;
    const int bn = blockIdx.y * 128;
    const int tx = tid & 15;
    const int ty = tid >> 4;
    float acc[8][8];
#pragma unroll
    for (int i = 0; i < 8; i++)
#pragma unroll
        for (int j = 0; j < 8; j++) acc[i][j] = 0.f;

    const int ar = tid >> 2;        // 0..63
    const int ac = (tid & 3) << 2;  // 0,4,8,12
    const int br = tid >> 5;        // 0..7
    const int bc = (tid & 31) << 2; // 0..124

    for (int k0 = 0; k0 < K; k0 += 16) {
#pragma unroll
        for (int h = 0; h < 2; h++) {
            int row = bm + ar + h * 64;
            float4 v = make_float4(0.f, 0.f, 0.f, 0.f);
            if (row < M)
                v = *reinterpret_cast<const float4*>(A + (size_t)row * K + k0 + ac);
            As[ac + 0][ar + h * 64] = v.x;
            As[ac + 1][ar + h * 64] = v.y;
            As[ac + 2][ar + h * 64] = v.z;
            As[ac + 3][ar + h * 64] = v.w;
        }
#pragma unroll
        for (int h = 0; h < 2; h++) {
            *reinterpret_cast<float4*>(&Bs[br + h * 8][bc]) =
                *reinterpret_cast<const float4*>(Bt + (size_t)(k0 + br + h * 8) * Nc + bn + bc);
        }
        __syncthreads();
#pragma unroll
        for (int k = 0; k < 16; k++) {
            float a[8], b[8];
#pragma unroll
            for (int i = 0; i < 8; i++) a[i] = As[k][ty * 8 + i];
#pragma unroll
            for (int j = 0; j < 8; j++) b[j] = Bs[k][tx * 8 + j];
#pragma unroll
            for (int i = 0; i < 8; i++)
#pragma unroll
                for (int j = 0; j < 8; j++) acc[i][j] = fmaf(a[i], b[j], acc[i][j]);
        }
        __syncthreads();
    }
#pragma unroll
    for (int i = 0; i < 8; i++) {
        int row = bm + ty * 8 + i;
        if (row >= M) continue;
        float* cp = C + (size_t)row * Nc + bn + tx * 8;
        *reinterpret_cast<float4*>(cp)     = make_float4(acc[i][0], acc[i][1], acc[i][2], acc[i][3]);
        *reinterpret_cast<float4*>(cp + 4) = make_float4(acc[i][4], acc[i][5], acc[i][6], acc[i][7]);
    }
}

// ---------------- GRU pointwise cell ----------------
__global__ void gru_cell_k(const float* __restrict__ gi, const float* __restrict__ gh,
                           const float* __restrict__ bih, const float* __restrict__ bhh,
                           float* __restrict__ h, float* __restrict__ out0, int t) {
    int idx = blockIdx.x * blockDim.x + threadIdx.x;
    if (idx >= NN * HH) return;
    int i = idx >> 7;
    int j = idx & 127;
    size_t mg = ((size_t)i * TT + t) * G3;
    size_t hg = (size_t)i * G3;
    float ir  = gi[mg + j]          + bih[j];
    float iz  = gi[mg + HH + j]     + bih[HH + j];
    float inn = gi[mg + 2 * HH + j] + bih[2 * HH + j];
    float hr  = gh[hg + j]          + bhh[j];
    float hz  = gh[hg + HH + j]     + bhh[HH + j];
    float hn  = gh[hg + 2 * HH + j] + bhh[2 * HH + j];
    float r = 1.f / (1.f + expf(-(ir + hr)));
    float z = 1.f / (1.f + expf(-(iz + hz)));
    float n = tanhf(inn + r * hn);
    float hold = h[idx];
    float hnew = (1.f - z) * n + z * hold;
    h[idx] = hnew;
    if (out0) out0[((size_t)i * TT + t) * HH + j] = hnew;
}

// ---------------- GAT kernels (generic over node count / edge count) ----------------
// per-node attention scores + self-loop max init (one warp per node)
__global__ void gat_scores_k(const float* __restrict__ hlin,
                             const float* __restrict__ asrc, const float* __restrict__ adst,
                             float* __restrict__ es, float* __restrict__ ed,
                             unsigned* __restrict__ mu, int n) {
    int g = blockIdx.x * blockDim.x + threadIdx.x;
    int node = g >> 5;
    int lane = g & 31;
    if (node >= n) return;
    float4 h4 = reinterpret_cast<const float4*>(hlin + (size_t)node * HH)[lane];
    float4 a4 = reinterpret_cast<const float4*>(asrc)[lane];
    float4 d4 = reinterpret_cast<const float4*>(adst)[lane];
    float s = h4.x * a4.x + h4.y * a4.y + h4.z * a4.z + h4.w * a4.w;
    float d = h4.x * d4.x + h4.y * d4.y + h4.z * d4.z + h4.w * d4.w;
#pragma unroll
    for (int o = 16; o; o >>= 1) {
        s += __shfl_xor_sync(0xffffffffu, s, o);
        d += __shfl_xor_sync(0xffffffffu, d, o);
    }
    if (lane == 0) {
        es[node] = s;
        ed[node] = d;
        mu[node] = fkey(lrelu(s + d));  // self-loop seeds the segment max
    }
}

__global__ void gat_edge_max_k(const int* __restrict__ ei,
                               const float* __restrict__ es, const float* __restrict__ ed,
                               float* __restrict__ eedge, unsigned* __restrict__ mu, int E) {
    int e = blockIdx.x * blockDim.x + threadIdx.x;
    if (e >= E) return;
    int s = ei[e];
    int d = ei[E + e];
    float v = lrelu(es[s] + ed[d]);
    eedge[e] = v;
    atomicMax(&mu[d], fkey(v));
}

// finalize max; init denom & unnormalized accumulator with self-loop term
__global__ void gat_node_init_k(const float* __restrict__ hlin,
                                const float* __restrict__ es, const float* __restrict__ ed,
                                const unsigned* __restrict__ mu,
                                float* __restrict__ m, float* __restrict__ den,
                                float* __restrict__ acc) {
    int i = blockIdx.x;
    int j = threadIdx.x;
    float mv = funkey(mu[i]);
    float w0 = expf(lrelu(es[i] + ed[i]) - mv);
    if (j == 0) { m[i] = mv; den[i] = w0; }
    acc[(size_t)i * HH + j] = w0 * hlin[(size_t)i * HH + j];
}

// one warp per edge: w = exp(e - m[dst]); denom += w; acc[dst] += w * hlin[src]
__global__ void gat_edge_agg_k(const int* __restrict__ ei, const float* __restrict__ eedge,
                               const float* __restrict__ m, const float* __restrict__ hlin,
                               float* __restrict__ den, float* __restrict__ acc, int E) {
    int g = blockIdx.x * blockDim.x + threadIdx.x;
    int e = g >> 5;
    int lane = g & 31;
    if (e >= E) return;
    int s = ei[e];
    int d = ei[E + e];
    float w = expf(eedge[e] - m[d]);
    if (lane == 0) atomicAdd(&den[d], w);
    float4 hv = reinterpret_cast<const float4*>(hlin + (size_t)s * HH)[lane];
    float* ap = acc + (size_t)d * HH + 4 * lane;
    atomicAdd(ap + 0, w * hv.x);
    atomicAdd(ap + 1, w * hv.y);
    atomicAdd(ap + 2, w * hv.z);
    atomicAdd(ap + 3, w * hv.w);
}

__global__ void gat_finalize_k(float* __restrict__ acc, const float* __restrict__ den,
                               const float* __restrict__ bias) {
    int i = blockIdx.x;
    int j = threadIdx.x;
    acc[(size_t)i * HH + j] = acc[(size_t)i * HH + j] / den[i] + bias[j];
}

// ---------------- sector max pool ----------------
__global__ void pool_max_k(const float* __restrict__ x, const int* __restrict__ sid,
                           unsigned* __restrict__ pu) {
    int idx = blockIdx.x * blockDim.x + threadIdx.x;
    if (idx >= NN * HH) return;
    int i = idx >> 7;
    int j = idx & 127;
    atomicMax(&pu[sid[i] * HH + j], fkey(x[idx]));
}
__global__ void pool_conv_k(const unsigned* __restrict__ pu, float* __restrict__ p) {
    int idx = blockIdx.x * blockDim.x + threadIdx.x;
    if (idx < SS * HH) p[idx] = funkey(pu[idx]);
}

// ---------------- fusion head (one warp per company) ----------------
__global__ void fusion_k(const float* __restrict__ seq, const float* __restrict__ intra,
                         const float* __restrict__ inter, const int* __restrict__ sid,
                         const float* __restrict__ fw, const float* __restrict__ fb,
                         float* __restrict__ out) {
    int g = blockIdx.x * blockDim.x + threadIdx.x;
    int i = g >> 5;
    int lane = g & 31;
    if (i >= NN) return;
    int sc = sid[i];
    const float4* s4 = reinterpret_cast<const float4*>(seq + (size_t)i * HH);
    const float4* i4 = reinterpret_cast<const float4*>(intra + (size_t)i * HH);
    const float4* e4 = reinterpret_cast<const float4*>(inter + (size_t)sc * HH);
    const float4* w4 = reinterpret_cast<const float4*>(fw);
    float sum = 0.f;
    float4 a, b;
    a = s4[lane]; b = w4[lane];
    sum += a.x * b.x + a.y * b.y + a.z * b.z + a.w * b.w;
    a = i4[lane]; b = w4[32 + lane];
    sum += a.x * b.x + a.y * b.y + a.z * b.z + a.w * b.w;
    a = e4[lane]; b = w4[64 + lane];
    sum += a.x * b.x + a.y * b.y + a.z * b.z + a.w * b.w;
#pragma unroll
    for (int o = 16; o; o >>= 1) sum += __shfl_xor_sync(0xffffffffu, sum, o);
    if (lane == 0) out[i] = sum + fb[0];
}

// ---------------- host ----------------
static inline void launch_sgemm(const float* A, const float* Bt, float* C,
                                int M, int Nc, int K) {
    dim3 grid((M + 127) / 128, Nc / 128);
    sgemm_k<<<grid, 256>>>(A, Bt, C, M, Nc, K);
}

extern "C" void kernel_launch(void* const* d_in, const int* in_sizes, int n_in,
                              void* d_out, int out_size) {
    const float* x        = (const float*)d_in[0];
    const int*   ei_intra = (const int*)d_in[1];
    const int*   ei_inter = (const int*)d_in[2];
    const int*   sid      = (const int*)d_in[3];
    const float* w_ih0 = (const float*)d_in[4];
    const float* w_hh0 = (const float*)d_in[5];
    const float* b_ih0 = (const float*)d_in[6];
    const float* b_hh0 = (const float*)d_in[7];
    const float* w_ih1 = (const float*)d_in[8];
    const float* w_hh1 = (const float*)d_in[9];
    const float* b_ih1 = (const float*)d_in[10];
    const float* b_hh1 = (const float*)d_in[11];
    const float* intra_W  = (const float*)d_in[12];
    const float* a_src_i  = (const float*)d_in[13];
    const float* a_dst_i  = (const float*)d_in[14];
    const float* bias_i   = (const float*)d_in[15];
    const float* inter_W  = (const float*)d_in[16];
    const float* a_src_e  = (const float*)d_in[17];
    const float* a_dst_e  = (const float*)d_in[18];
    const float* bias_e   = (const float*)d_in[19];
    const float* fw       = (const float*)d_in[20];
    const float* fb       = (const float*)d_in[21];
    float* out = (float*)d_out;

    float *gi, *o0, *gh, *h0, *h1, *hlin, *acc;
    float *bt_ih0, *bt_hh0, *bt_ih1, *bt_hh1, *bt_a, *bt_e;
    float *es, *ed, *m, *den, *eedge, *pool, *shlin, *sacc;
    unsigned *mu, *pu;
    cudaGetSymbolAddress((void**)&gi, g_gi);
    cudaGetSymbolAddress((void**)&o0, g_out0);
    cudaGetSymbolAddress((void**)&gh, g_gh);
    cudaGetSymbolAddress((void**)&h0, g_h0);
    cudaGetSymbolAddress((void**)&h1, g_h1);
    cudaGetSymbolAddress((void**)&hlin, g_hlin);
    cudaGetSymbolAddress((void**)&acc, g_acc);
    cudaGetSymbolAddress((void**)&bt_ih0, g_Bt_ih0);
    cudaGetSymbolAddress((void**)&bt_hh0, g_Bt_hh0);
    cudaGetSymbolAddress((void**)&bt_ih1, g_Bt_ih1);
    cudaGetSymbolAddress((void**)&bt_hh1, g_Bt_hh1);
    cudaGetSymbolAddress((void**)&bt_a, g_Bt_intra);
    cudaGetSymbolAddress((void**)&bt_e, g_Bt_inter);
    cudaGetSymbolAddress((void**)&es, g_es);
    cudaGetSymbolAddress((void**)&ed, g_ed);
    cudaGetSymbolAddress((void**)&m, g_m);
    cudaGetSymbolAddress((void**)&den, g_den);
    cudaGetSymbolAddress((void**)&mu, g_mu);
    cudaGetSymbolAddress((void**)&eedge, g_eedge);
    cudaGetSymbolAddress((void**)&pu, g_pu);
    cudaGetSymbolAddress((void**)&pool, g_pool);
    cudaGetSymbolAddress((void**)&shlin, g_shlin);
    cudaGetSymbolAddress((void**)&sacc, g_sacc);

    // ---- prep: transpose weights, zero hidden states ----
    transpose_k<<<(G3 * INP + 255) / 256, 256>>>(w_ih0, bt_ih0, G3, INP);
    transpose_k<<<(G3 * HH + 255) / 256, 256>>>(w_hh0, bt_hh0, G3, HH);
    transpose_k<<<(G3 * HH + 255) / 256, 256>>>(w_ih1, bt_ih1, G3, HH);
    transpose_k<<<(G3 * HH + 255) / 256, 256>>>(w_hh1, bt_hh1, G3, HH);
    transpose_k<<<(HH * HH + 255) / 256, 256>>>(intra_W, bt_a, HH, HH);
    transpose_k<<<(HH * HH + 255) / 256, 256>>>(inter_W, bt_e, HH, HH);
    zerof_k<<<(NN * HH + 255) / 256, 256>>>(h0, NN * HH);
    zerof_k<<<(NN * HH + 255) / 256, 256>>>(h1, NN * HH);

    const int cellGrid = (NN * HH + 255) / 256;

    // ---- GRU layer 0 ----
    launch_sgemm(x, bt_ih0, gi, NN * TT, G3, INP);   // gi = x @ W_ih0^T (all t)
    for (int t = 0; t < TT; t++) {
        launch_sgemm(h0, bt_hh0, gh, NN, G3, HH);    // gh = h @ W_hh0^T
        gru_cell_k<<<cellGrid, 256>>>(gi, gh, b_ih0, b_hh0, h0, o0, t);
    }
    // ---- GRU layer 1 ----
    launch_sgemm(o0, bt_ih1, gi, NN * TT, G3, HH);   // gi = out0 @ W_ih1^T (all t)
    for (int t = 0; t < TT; t++) {
        launch_sgemm(h1, bt_hh1, gh, NN, G3, HH);
        gru_cell_k<<<cellGrid, 256>>>(gi, gh, b_ih1, b_hh1, h1, nullptr, t);
    }
    // h1 == seq_emb

    // ---- intra GAT ----
    launch_sgemm(h1, bt_a, hlin, NN, HH, HH);
    gat_scores_k<<<(NN * 32 + 255) / 256, 256>>>(hlin, a_src_i, a_dst_i, es, ed, mu, NN);
    gat_edge_max_k<<<(EINTRA + 255) / 256, 256>>>(ei_intra, es, ed, eedge, mu, EINTRA);
    gat_node_init_k<<<NN, HH>>>(hlin, es, ed, mu, m, den, acc);
    gat_edge_agg_k<<<(EINTRA * 32 + 255) / 256, 256>>>(ei_intra, eedge, m, hlin, den, acc, EINTRA);
    gat_finalize_k<<<NN, HH>>>(acc, den, bias_i);
    // acc == intra_emb

    // ---- sector max pool ----
    zerou_k<<<(SS * HH + 255) / 256, 256>>>(pu, SS * HH);
    pool_max_k<<<(NN * HH + 255) / 256, 256>>>(acc, sid, pu);
    pool_conv_k<<<(SS * HH + 255) / 256, 256>>>(pu, pool);

    // ---- inter GAT (S=64) ----
    launch_sgemm(pool, bt_e, shlin, SS, HH, HH);
    gat_scores_k<<<(SS * 32 + 255) / 256, 256>>>(shlin, a_src_e, a_dst_e, es, ed, mu, SS);
    gat_edge_max_k<<<(EINTER + 255) / 256, 256>>>(ei_inter, es, ed, eedge, mu, EINTER);
    gat_node_init_k<<<SS, HH>>>(shlin, es, ed, mu, m, den, sacc);
    gat_edge_agg_k<<<(EINTER * 32 + 255) / 256, 256>>>(ei_inter, eedge, m, shlin, den, sacc, EINTER);
    gat_finalize_k<<<SS, HH>>>(sacc, den, bias_e);
    // sacc == inter_sec

    // ---- fusion ----
    fusion_k<<<(NN * 32 + 255) / 256, 256>>>(h1, acc, sacc, sid, fw, fb, out);
}

// round 2
// speedup vs baseline: 1.0524x; 1.0524x over previous
#include <cuda_runtime.h>
#include <math.h>

#define NN     20000
#define TT     32
#define INP    64
#define HH     128
#define G3     384
#define SS     64
#define EINTRA 640000
#define EINTER 4096

// ---------------- scratch (static device globals; no allocs) ----------------
__device__ __align__(128) float    g_gi[(size_t)NN*TT*G3];   // 983 MB, reused by both layers
__device__ __align__(128) float    g_out0[(size_t)NN*TT*HH]; // 328 MB layer0 outputs
__device__ __align__(128) float    g_gh[(size_t)NN*G3];
__device__ __align__(128) float    g_h0[(size_t)NN*HH];
__device__ __align__(128) float    g_h1[(size_t)NN*HH];
__device__ __align__(128) float    g_hlin[(size_t)NN*HH];
__device__ __align__(128) float    g_acc[(size_t)NN*HH];     // intra_emb
__device__ __align__(128) float    g_Bt_ih0[INP*G3];
__device__ __align__(128) float    g_Bt_hh0[HH*G3];
__device__ __align__(128) float    g_Bt_ih1[HH*G3];
__device__ __align__(128) float    g_Bt_hh1[HH*G3];
__device__ __align__(128) float    g_Bt_intra[HH*HH];
__device__ __align__(128) float    g_Bt_inter[HH*HH];
__device__ float    g_es[NN];
__device__ float    g_ed[NN];
__device__ float    g_m[NN];
__device__ float    g_den[NN];
__device__ unsigned g_mu[NN];
__device__ float    g_eedge[EINTRA];
__device__ unsigned g_pu[SS*HH];
__device__ __align__(128) float g_pool[SS*HH];
__device__ __align__(128) float g_shlin[SS*HH];
__device__ __align__(128) float g_sacc[SS*HH];               // inter_sec

// ---------------- helpers ----------------
__device__ __forceinline__ unsigned fkey(float f) {
    unsigned u = __float_as_uint(f);
    return (u & 0x80000000u) ? ~u : (u | 0x80000000u);
}
__device__ __forceinline__ float funkey(unsigned k) {
    return (k & 0x80000000u) ? __uint_as_float(k & 0x7fffffffu)
                             : __uint_as_float(~k);
}
__device__ __forceinline__ float lrelu(float x) { return x > 0.f ? x : 0.2f * x; }

// packed f32x2 FMA (sm_103a FFMA2 — only reachable via PTX)
__device__ __forceinline__ void ffma2(unsigned long long& d,
                                      unsigned long long a,
                                      unsigned long long b) {
    asm("fma.rn.f32x2 %0, %1, %2, %0;" : "+l"(d) : "l"(a), "l"(b));
}
__device__ __forceinline__ unsigned long long pack2(float lo, float hi) {
    unsigned long long r;
    asm("mov.b64 %0, {%1, %2};" : "=l"(r) : "f"(lo), "f"(hi));
    return r;
}
__device__ __forceinline__ void unpack2(unsigned long long v, float& lo, float& hi) {
    asm("mov.b64 {%0, %1}, %2;" : "=f"(lo), "=f"(hi) : "l"(v));
}

// ---------------- misc kernels ----------------
__global__ void zerof_k(float* p, int n) {
    int i = blockIdx.x * blockDim.x + threadIdx.x;
    if (i < n) p[i] = 0.f;
}
__global__ void zerou_k(unsigned* p, int n) {
    int i = blockIdx.x * blockDim.x + threadIdx.x;
    if (i < n) p[i] = 0u;
}
// W: [nrows, ncols] row-major -> Bt: [ncols, nrows] row-major (Bt[k][j] = W[j][k])
__global__ void transpose_k(const float* __restrict__ W, float* __restrict__ Bt,
                            int nrows, int ncols) {
    int idx = blockIdx.x * blockDim.x + threadIdx.x;
    if (idx >= nrows * ncols) return;
    int j = idx / ncols;
    int k = idx % ncols;
    Bt[k * nrows + j] = W[idx];
}

// ---------------- SGEMM (FFMA2): C[M,Nc] = A[M,K] @ Bt[K,Nc] ----------------
// BM=BN=128, BK=16, 256 threads. Each thread: 8 rows (4 row-pairs) x 8 cols,
// accumulated in packed f32x2 registers. A fragments load as 64-bit row-pairs
// straight from shared; B values broadcast-packed {b,b}.
__global__ void __launch_bounds__(256) sgemm_k(const float* __restrict__ A,
                                               const float* __restrict__ Bt,
                                               float* __restrict__ C,
                                               int M, int Nc, int K) {
    __shared__ float As[16][132];   // k-major, m contiguous (pad keeps 16B align: 132*4=528)
    __shared__ float Bs[16][128];
    const int tid = threadIdx.x;
    const int bm = blockIdx.x * 128;
    const int bn = blockIdx.y * 128;
    const int tx = tid & 15;        // col group (8 cols)
    const int ty = tid >> 4;        // row group (8 rows = 4 pairs)

    unsigned long long acc[4][8];
#pragma unroll
    for (int i = 0; i < 4; i++)
#pragma unroll
        for (int j = 0; j < 8; j++) acc[i][j] = 0ull;

    const int ar = tid >> 2;        // 0..63
    const int ac = (tid & 3) << 2;  // 0,4,8,12
    const int br = tid >> 5;        // 0..7
    const int bc = (tid & 31) << 2; // 0..124

    for (int k0 = 0; k0 < K; k0 += 16) {
#pragma unroll
        for (int h = 0; h < 2; h++) {
            int row = bm + ar + h * 64;
            float4 v = make_float4(0.f, 0.f, 0.f, 0.f);
            if (row < M)
                v = *reinterpret_cast<const float4*>(A + (size_t)row * K + k0 + ac);
            As[ac + 0][ar + h * 64] = v.x;
            As[ac + 1][ar + h * 64] = v.y;
            As[ac + 2][ar + h * 64] = v.z;
            As[ac + 3][ar + h * 64] = v.w;
        }
#pragma unroll
        for (int h = 0; h < 2; h++) {
            *reinterpret_cast<float4*>(&Bs[br + h * 8][bc]) =
                *reinterpret_cast<const float4*>(Bt + (size_t)(k0 + br + h * 8) * Nc + bn + bc);
        }
        __syncthreads();
#pragma unroll
        for (int k = 0; k < 16; k++) {
            const unsigned long long* ap =
                reinterpret_cast<const unsigned long long*>(&As[k][ty * 8]);
            unsigned long long a0 = ap[0];
            unsigned long long a1 = ap[1];
            unsigned long long a2 = ap[2];
            unsigned long long a3 = ap[3];
            float4 bA = *reinterpret_cast<const float4*>(&Bs[k][tx * 8]);
            float4 bB = *reinterpret_cast<const float4*>(&Bs[k][tx * 8 + 4]);
            unsigned long long bb[8];
            bb[0] = pack2(bA.x, bA.x);
            bb[1] = pack2(bA.y, bA.y);
            bb[2] = pack2(bA.z, bA.z);
            bb[3] = pack2(bA.w, bA.w);
            bb[4] = pack2(bB.x, bB.x);
            bb[5] = pack2(bB.y, bB.y);
            bb[6] = pack2(bB.z, bB.z);
            bb[7] = pack2(bB.w, bB.w);
#pragma unroll
            for (int j = 0; j < 8; j++) {
                ffma2(acc[0][j], a0, bb[j]);
                ffma2(acc[1][j], a1, bb[j]);
                ffma2(acc[2][j], a2, bb[j]);
                ffma2(acc[3][j], a3, bb[j]);
            }
        }
        __syncthreads();
    }

    // epilogue: each acc[ip][j] holds rows (ty*8+2ip, ty*8+2ip+1), col tx*8+j
#pragma unroll
    for (int ip = 0; ip < 4; ip++) {
        float lo[8], hi[8];
#pragma unroll
        for (int j = 0; j < 8; j++) unpack2(acc[ip][j], lo[j], hi[j]);
        int r0 = bm + ty * 8 + 2 * ip;
        if (r0 < M) {
            float* cp = C + (size_t)r0 * Nc + bn + tx * 8;
            *reinterpret_cast<float4*>(cp)     = make_float4(lo[0], lo[1], lo[2], lo[3]);
            *reinterpret_cast<float4*>(cp + 4) = make_float4(lo[4], lo[5], lo[6], lo[7]);
        }
        int r1 = r0 + 1;
        if (r1 < M) {
            float* cp = C + (size_t)r1 * Nc + bn + tx * 8;
            *reinterpret_cast<float4*>(cp)     = make_float4(hi[0], hi[1], hi[2], hi[3]);
            *reinterpret_cast<float4*>(cp + 4) = make_float4(hi[4], hi[5], hi[6], hi[7]);
        }
    }
}

// ---------------- GRU pointwise cell ----------------
__global__ void gru_cell_k(const float* __restrict__ gi, const float* __restrict__ gh,
                           const float* __restrict__ bih, const float* __restrict__ bhh,
                           float* __restrict__ h, float* __restrict__ out0, int t) {
    int idx = blockIdx.x * blockDim.x + threadIdx.x;
    if (idx >= NN * HH) return;
    int i = idx >> 7;
    int j = idx & 127;
    size_t mg = ((size_t)i * TT + t) * G3;
    size_t hg = (size_t)i * G3;
    float ir  = gi[mg + j]          + bih[j];
    float iz  = gi[mg + HH + j]     + bih[HH + j];
    float inn = gi[mg + 2 * HH + j] + bih[2 * HH + j];
    float hr  = gh[hg + j]          + bhh[j];
    float hz  = gh[hg + HH + j]     + bhh[HH + j];
    float hn  = gh[hg + 2 * HH + j] + bhh[2 * HH + j];
    float r = 1.f / (1.f + expf(-(ir + hr)));
    float z = 1.f / (1.f + expf(-(iz + hz)));
    float n = tanhf(inn + r * hn);
    float hold = h[idx];
    float hnew = (1.f - z) * n + z * hold;
    h[idx] = hnew;
    if (out0) out0[((size_t)i * TT + t) * HH + j] = hnew;
}

// ---------------- GAT kernels (generic over node count / edge count) ----------------
__global__ void gat_scores_k(const float* __restrict__ hlin,
                             const float* __restrict__ asrc, const float* __restrict__ adst,
                             float* __restrict__ es, float* __restrict__ ed,
                             unsigned* __restrict__ mu, int n) {
    int g = blockIdx.x * blockDim.x + threadIdx.x;
    int node = g >> 5;
    int lane = g & 31;
    if (node >= n) return;
    float4 h4 = reinterpret_cast<const float4*>(hlin + (size_t)node * HH)[lane];
    float4 a4 = reinterpret_cast<const float4*>(asrc)[lane];
    float4 d4 = reinterpret_cast<const float4*>(adst)[lane];
    float s = h4.x * a4.x + h4.y * a4.y + h4.z * a4.z + h4.w * a4.w;
    float d = h4.x * d4.x + h4.y * d4.y + h4.z * d4.z + h4.w * d4.w;
#pragma unroll
    for (int o = 16; o; o >>= 1) {
        s += __shfl_xor_sync(0xffffffffu, s, o);
        d += __shfl_xor_sync(0xffffffffu, d, o);
    }
    if (lane == 0) {
        es[node] = s;
        ed[node] = d;
        mu[node] = fkey(lrelu(s + d));  // self-loop seeds the segment max
    }
}

__global__ void gat_edge_max_k(const int* __restrict__ ei,
                               const float* __restrict__ es, const float* __restrict__ ed,
                               float* __restrict__ eedge, unsigned* __restrict__ mu, int E) {
    int e = blockIdx.x * blockDim.x + threadIdx.x;
    if (e >= E) return;
    int s = ei[e];
    int d = ei[E + e];
    float v = lrelu(es[s] + ed[d]);
    eedge[e] = v;
    atomicMax(&mu[d], fkey(v));
}

__global__ void gat_node_init_k(const float* __restrict__ hlin,
                                const float* __restrict__ es, const float* __restrict__ ed,
                                const unsigned* __restrict__ mu,
                                float* __restrict__ m, float* __restrict__ den,
                                float* __restrict__ acc) {
    int i = blockIdx.x;
    int j = threadIdx.x;
    float mv = funkey(mu[i]);
    float w0 = expf(lrelu(es[i] + ed[i]) - mv);
    if (j == 0) { m[i] = mv; den[i] = w0; }
    acc[(size_t)i * HH + j] = w0 * hlin[(size_t)i * HH + j];
}

__global__ void gat_edge_agg_k(const int* __restrict__ ei, const float* __restrict__ eedge,
                               const float* __restrict__ m, const float* __restrict__ hlin,
                               float* __restrict__ den, float* __restrict__ acc, int E) {
    int g = blockIdx.x * blockDim.x + threadIdx.x;
    int e = g >> 5;
    int lane = g & 31;
    if (e >= E) return;
    int s = ei[e];
    int d = ei[E + e];
    float w = expf(eedge[e] - m[d]);
    if (lane == 0) atomicAdd(&den[d], w);
    float4 hv = reinterpret_cast<const float4*>(hlin + (size_t)s * HH)[lane];
    float* ap = acc + (size_t)d * HH + 4 * lane;
    atomicAdd(ap + 0, w * hv.x);
    atomicAdd(ap + 1, w * hv.y);
    atomicAdd(ap + 2, w * hv.z);
    atomicAdd(ap + 3, w * hv.w);
}

__global__ void gat_finalize_k(float* __restrict__ acc, const float* __restrict__ den,
                               const float* __restrict__ bias) {
    int i = blockIdx.x;
    int j = threadIdx.x;
    acc[(size_t)i * HH + j] = acc[(size_t)i * HH + j] / den[i] + bias[j];
}

// ---------------- sector max pool ----------------
__global__ void pool_max_k(const float* __restrict__ x, const int* __restrict__ sid,
                           unsigned* __restrict__ pu) {
    int idx = blockIdx.x * blockDim.x + threadIdx.x;
    if (idx >= NN * HH) return;
    int i = idx >> 7;
    int j = idx & 127;
    atomicMax(&pu[sid[i] * HH + j], fkey(x[idx]));
}
__global__ void pool_conv_k(const unsigned* __restrict__ pu, float* __restrict__ p) {
    int idx = blockIdx.x * blockDim.x + threadIdx.x;
    if (idx < SS * HH) p[idx] = funkey(pu[idx]);
}

// ---------------- fusion head (one warp per company) ----------------
__global__ void fusion_k(const float* __restrict__ seq, const float* __restrict__ intra,
                         const float* __restrict__ inter, const int* __restrict__ sid,
                         const float* __restrict__ fw, const float* __restrict__ fb,
                         float* __restrict__ out) {
    int g = blockIdx.x * blockDim.x + threadIdx.x;
    int i = g >> 5;
    int lane = g & 31;
    if (i >= NN) return;
    int sc = sid[i];
    const float4* s4 = reinterpret_cast<const float4*>(seq + (size_t)i * HH);
    const float4* i4 = reinterpret_cast<const float4*>(intra + (size_t)i * HH);
    const float4* e4 = reinterpret_cast<const float4*>(inter + (size_t)sc * HH);
    const float4* w4 = reinterpret_cast<const float4*>(fw);
    float sum = 0.f;
    float4 a, b;
    a = s4[lane]; b = w4[lane];
    sum += a.x * b.x + a.y * b.y + a.z * b.z + a.w * b.w;
    a = i4[lane]; b = w4[32 + lane];
    sum += a.x * b.x + a.y * b.y + a.z * b.z + a.w * b.w;
    a = e4[lane]; b = w4[64 + lane];
    sum += a.x * b.x + a.y * b.y + a.z * b.z + a.w * b.w;
#pragma unroll
    for (int o = 16; o; o >>= 1) sum += __shfl_xor_sync(0xffffffffu, sum, o);
    if (lane == 0) out[i] = sum + fb[0];
}

// ---------------- host ----------------
static inline void launch_sgemm(const float* A, const float* Bt, float* C,
                                int M, int Nc, int K) {
    dim3 grid((M + 127) / 128, Nc / 128);
    sgemm_k<<<grid, 256>>>(A, Bt, C, M, Nc, K);
}

extern "C" void kernel_launch(void* const* d_in, const int* in_sizes, int n_in,
                              void* d_out, int out_size) {
    const float* x        = (const float*)d_in[0];
    const int*   ei_intra = (const int*)d_in[1];
    const int*   ei_inter = (const int*)d_in[2];
    const int*   sid      = (const int*)d_in[3];
    const float* w_ih0 = (const float*)d_in[4];
    const float* w_hh0 = (const float*)d_in[5];
    const float* b_ih0 = (const float*)d_in[6];
    const float* b_hh0 = (const float*)d_in[7];
    const float* w_ih1 = (const float*)d_in[8];
    const float* w_hh1 = (const float*)d_in[9];
    const float* b_ih1 = (const float*)d_in[10];
    const float* b_hh1 = (const float*)d_in[11];
    const float* intra_W  = (const float*)d_in[12];
    const float* a_src_i  = (const float*)d_in[13];
    const float* a_dst_i  = (const float*)d_in[14];
    const float* bias_i   = (const float*)d_in[15];
    const float* inter_W  = (const float*)d_in[16];
    const float* a_src_e  = (const float*)d_in[17];
    const float* a_dst_e  = (const float*)d_in[18];
    const float* bias_e   = (const float*)d_in[19];
    const float* fw       = (const float*)d_in[20];
    const float* fb       = (const float*)d_in[21];
    float* out = (float*)d_out;

    float *gi, *o0, *gh, *h0, *h1, *hlin, *acc;
    float *bt_ih0, *bt_hh0, *bt_ih1, *bt_hh1, *bt_a, *bt_e;
    float *es, *ed, *m, *den, *eedge, *pool, *shlin, *sacc;
    unsigned *mu, *pu;
    cudaGetSymbolAddress((void**)&gi, g_gi);
    cudaGetSymbolAddress((void**)&o0, g_out0);
    cudaGetSymbolAddress((void**)&gh, g_gh);
    cudaGetSymbolAddress((void**)&h0, g_h0);
    cudaGetSymbolAddress((void**)&h1, g_h1);
    cudaGetSymbolAddress((void**)&hlin, g_hlin);
    cudaGetSymbolAddress((void**)&acc, g_acc);
    cudaGetSymbolAddress((void**)&bt_ih0, g_Bt_ih0);
    cudaGetSymbolAddress((void**)&bt_hh0, g_Bt_hh0);
    cudaGetSymbolAddress((void**)&bt_ih1, g_Bt_ih1);
    cudaGetSymbolAddress((void**)&bt_hh1, g_Bt_hh1);
    cudaGetSymbolAddress((void**)&bt_a, g_Bt_intra);
    cudaGetSymbolAddress((void**)&bt_e, g_Bt_inter);
    cudaGetSymbolAddress((void**)&es, g_es);
    cudaGetSymbolAddress((void**)&ed, g_ed);
    cudaGetSymbolAddress((void**)&m, g_m);
    cudaGetSymbolAddress((void**)&den, g_den);
    cudaGetSymbolAddress((void**)&mu, g_mu);
    cudaGetSymbolAddress((void**)&eedge, g_eedge);
    cudaGetSymbolAddress((void**)&pu, g_pu);
    cudaGetSymbolAddress((void**)&pool, g_pool);
    cudaGetSymbolAddress((void**)&shlin, g_shlin);
    cudaGetSymbolAddress((void**)&sacc, g_sacc);

    // ---- prep: transpose weights, zero hidden states ----
    transpose_k<<<(G3 * INP + 255) / 256, 256>>>(w_ih0, bt_ih0, G3, INP);
    transpose_k<<<(G3 * HH + 255) / 256, 256>>>(w_hh0, bt_hh0, G3, HH);
    transpose_k<<<(G3 * HH + 255) / 256, 256>>>(w_ih1, bt_ih1, G3, HH);
    transpose_k<<<(G3 * HH + 255) / 256, 256>>>(w_hh1, bt_hh1, G3, HH);
    transpose_k<<<(HH * HH + 255) / 256, 256>>>(intra_W, bt_a, HH, HH);
    transpose_k<<<(HH * HH + 255) / 256, 256>>>(inter_W, bt_e, HH, HH);
    zerof_k<<<(NN * HH + 255) / 256, 256>>>(h0, NN * HH);
    zerof_k<<<(NN * HH + 255) / 256, 256>>>(h1, NN * HH);

    const int cellGrid = (NN * HH + 255) / 256;

    // ---- GRU layer 0 ----
    launch_sgemm(x, bt_ih0, gi, NN * TT, G3, INP);   // gi = x @ W_ih0^T (all t)
    for (int t = 0; t < TT; t++) {
        launch_sgemm(h0, bt_hh0, gh, NN, G3, HH);    // gh = h @ W_hh0^T
        gru_cell_k<<<cellGrid, 256>>>(gi, gh, b_ih0, b_hh0, h0, o0, t);
    }
    // ---- GRU layer 1 ----
    launch_sgemm(o0, bt_ih1, gi, NN * TT, G3, HH);   // gi = out0 @ W_ih1^T (all t)
    for (int t = 0; t < TT; t++) {
        launch_sgemm(h1, bt_hh1, gh, NN, G3, HH);
        gru_cell_k<<<cellGrid, 256>>>(gi, gh, b_ih1, b_hh1, h1, nullptr, t);
    }
    // h1 == seq_emb

    // ---- intra GAT ----
    launch_sgemm(h1, bt_a, hlin, NN, HH, HH);
    gat_scores_k<<<(NN * 32 + 255) / 256, 256>>>(hlin, a_src_i, a_dst_i, es, ed, mu, NN);
    gat_edge_max_k<<<(EINTRA + 255) / 256, 256>>>(ei_intra, es, ed, eedge, mu, EINTRA);
    gat_node_init_k<<<NN, HH>>>(hlin, es, ed, mu, m, den, acc);
    gat_edge_agg_k<<<(EINTRA * 32 + 255) / 256, 256>>>(ei_intra, eedge, m, hlin, den, acc, EINTRA);
    gat_finalize_k<<<NN, HH>>>(acc, den, bias_i);
    // acc == intra_emb

    // ---- sector max pool ----
    zerou_k<<<(SS * HH + 255) / 256, 256>>>(pu, SS * HH);
    pool_max_k<<<(NN * HH + 255) / 256, 256>>>(acc, sid, pu);
    pool_conv_k<<<(SS * HH + 255) / 256, 256>>>(pu, pool);

    // ---- inter GAT (S=64) ----
    launch_sgemm(pool, bt_e, shlin, SS, HH, HH);
    gat_scores_k<<<(SS * 32 + 255) / 256, 256>>>(shlin, a_src_e, a_dst_e, es, ed, mu, SS);
    gat_edge_max_k<<<(EINTER + 255) / 256, 256>>>(ei_inter, es, ed, eedge, mu, EINTER);
    gat_node_init_k<<<SS, HH>>>(shlin, es, ed, mu, m, den, sacc);
    gat_edge_agg_k<<<(EINTER * 32 + 255) / 256, 256>>>(ei_inter, eedge, m, shlin, den, sacc, EINTER);
    gat_finalize_k<<<SS, HH>>>(sacc, den, bias_e);
    // sacc == inter_sec

    // ---- fusion ----
    fusion_k<<<(NN * 32 + 255) / 256, 256>>>(h1, acc, sacc, sid, fw, fb, out);
}

// round 5
// speedup vs baseline: 1.7025x; 1.6177x over previous
#include <cuda_runtime.h>
#include <cuda_bf16.h>
#include <math.h>
#include <stdint.h>

#define NN     20000
#define TT     32
#define INP    64
#define HH     128
#define G3     384
#define SS     64
#define EINTRA 640000
#define EINTER 4096

// ---------------- scratch (static device globals; no allocs) ----------------
__device__ __align__(128) float g_gi[(size_t)NN*TT*G3];            // 983 MB
__device__ __align__(128) __nv_bfloat16 g_xb[(size_t)NN*TT*2*INP]; // x as hi|lo
__device__ __align__(128) __nv_bfloat16 g_o0b[(size_t)NN*TT*2*HH]; // layer0 outputs hi|lo
__device__ __align__(128) float g_gh[(size_t)NN*G3];
__device__ __align__(128) float g_h[(size_t)NN*HH];
__device__ __align__(128) __nv_bfloat16 g_hb[(size_t)NN*2*HH];
__device__ __align__(128) float g_hlin[(size_t)NN*HH];
__device__ __align__(128) float g_acc[(size_t)NN*HH];
__device__ __align__(128) __nv_bfloat16 g_wb_ih0[G3*2*INP];
__device__ __align__(128) __nv_bfloat16 g_wb_hh0[G3*2*HH];
__device__ __align__(128) __nv_bfloat16 g_wb_ih1[G3*2*HH];
__device__ __align__(128) __nv_bfloat16 g_wb_hh1[G3*2*HH];
__device__ __align__(128) __nv_bfloat16 g_wb_intra[HH*2*HH];
__device__ __align__(128) __nv_bfloat16 g_wb_inter[HH*2*HH];
__device__ float    g_es[NN];
__device__ float    g_ed[NN];
__device__ float    g_m[NN];
__device__ float    g_den[NN];
__device__ unsigned g_mu[NN];
__device__ float    g_eedge[EINTRA];
__device__ unsigned g_pu[SS*HH];
__device__ __align__(128) float g_pool[SS*HH];
__device__ __align__(128) __nv_bfloat16 g_poolb[SS*2*HH];
__device__ __align__(128) float g_shlin[SS*HH];
__device__ __align__(128) float g_sacc[SS*HH];

// ---------------- helpers ----------------
__device__ __forceinline__ uint32_t smem_u32(const void* p) {
    uint32_t a;
    asm("{ .reg .u64 t; cvta.to.shared.u64 t, %1; cvt.u32.u64 %0, t; }" : "=r"(a) : "l"(p));
    return a;
}
__device__ __forceinline__ unsigned fkey(float f) {
    unsigned u = __float_as_uint(f);
    return (u & 0x80000000u) ? ~u : (u | 0x80000000u);
}
__device__ __forceinline__ float funkey(unsigned k) {
    return (k & 0x80000000u) ? __uint_as_float(k & 0x7fffffffu)
                             : __uint_as_float(~k);
}
__device__ __forceinline__ float lrelu(float x) { return x > 0.f ? x : 0.2f * x; }

__device__ __forceinline__ void cp_async16(uint32_t saddr, const void* gaddr, int srcBytes) {
    asm volatile("cp.async.cg.shared.global [%0], [%1], 16, %2;"
                 :: "r"(saddr), "l"(gaddr), "r"(srcBytes) : "memory");
}
__device__ __forceinline__ void cp_commit() {
    asm volatile("cp.async.commit_group;" ::: "memory");
}
template <int N>
__device__ __forceinline__ void cp_wait() {
    asm volatile("cp.async.wait_group %0;" :: "n"(N) : "memory");
}
__device__ __forceinline__ void ldmatrix_x4(uint32_t* r, uint32_t addr) {
    asm volatile("ldmatrix.sync.aligned.m8n8.x4.shared.b16 {%0,%1,%2,%3}, [%4];"
                 : "=r"(r[0]), "=r"(r[1]), "=r"(r[2]), "=r"(r[3]) : "r"(addr));
}
__device__ __forceinline__ void mma16816(float* d, const uint32_t* a, uint32_t b0, uint32_t b1) {
    asm volatile(
        "mma.sync.aligned.m16n8k16.row.col.f32.bf16.bf16.f32 "
        "{%0,%1,%2,%3}, {%4,%5,%6,%7}, {%8,%9}, {%0,%1,%2,%3};"
        : "+f"(d[0]), "+f"(d[1]), "+f"(d[2]), "+f"(d[3])
        : "r"(a[0]), "r"(a[1]), "r"(a[2]), "r"(a[3]), "r"(b0), "r"(b1));
}

// ---------------- misc kernels ----------------
__global__ void zerof_k(float* p, int n) {
    int i = blockIdx.x * blockDim.x + threadIdx.x;
    if (i < n) p[i] = 0.f;
}
__global__ void zerou_k(unsigned* p, int n) {
    int i = blockIdx.x * blockDim.x + threadIdx.x;
    if (i < n) p[i] = 0u;
}
// split fp32 [rows,K] -> bf16 [rows, 2K] as [hi | lo]
__global__ void convw_k(const float* __restrict__ W, __nv_bfloat16* __restrict__ Wb,
                        int rows, int K) {
    int idx = blockIdx.x * blockDim.x + threadIdx.x;
    if (idx >= rows * K) return;
    int r = idx / K, c = idx % K;
    float v = W[idx];
    __nv_bfloat16 hi = __float2bfloat16(v);
    __nv_bfloat16 lo = __float2bfloat16(v - __bfloat162float(hi));
    Wb[(size_t)r * 2 * K + c]     = hi;
    Wb[(size_t)r * 2 * K + K + c] = lo;
}

// ---------------- tensor-core GEMM (mma.sync bf16): C = split(A) @ split(B)^T ----
// Ab [M, 2K] bf16 (hi|lo), Bb [Nc, 2K] bf16 (hi|lo), C [M,Nc] fp32.
// Computes Ahi@Bhi^T + Alo@Bhi^T + Ahi@Blo^T. Tile 128x128xBK32, cp.async
// double buffer, XOR-swizzled smem, 8 warps each 32x64.
// grid = (Nc/128, ceil(M/128)); Nc % 128 == 0; K % 32 == 0.
__global__ void __launch_bounds__(256) gemm_mma_k(
    const __nv_bfloat16* __restrict__ Ab,
    const __nv_bfloat16* __restrict__ Bb,
    float* __restrict__ C, int M, int Nc, int K)
{
    __shared__ __align__(16) char smbuf[32768];  // [2 stages][A 8K | B 8K]
    const uint32_t sb = smem_u32(smbuf);
    const int tid = threadIdx.x;
    const int wid = tid >> 5, lane = tid & 31;
    const int wm = wid & 3;          // warp row  (32 rows)
    const int wn = wid >> 2;         // warp col  (64 cols)
    const int bm = blockIdx.y * 128;
    const int bn = blockIdx.x * 128;
    const int ldab = 2 * K;          // bf16 elems per row of Ab/Bb

    const int cpk = K >> 5;          // 32-elem chunks per K segment
    const int nk = 3 * cpk;

    float d[2][8][4];
#pragma unroll
    for (int i = 0; i < 2; i++)
#pragma unroll
        for (int j = 0; j < 8; j++)
#pragma unroll
            for (int q = 0; q < 4; q++) d[i][j][q] = 0.f;

    // load indexing: 512 16B-chunks per operand tile, 2 per thread
    // chunk cid: row = cid>>2, c = cid&3 (16B units within the 64B k-block)
    // smem off = row*64 + ((c ^ ((row>>1)&3))<<4)
    auto issue_loads = [&](int kb, int s) {
        const int seg = kb / cpk, kc = kb - seg * cpk;
        const int acol = (seg == 1 ? K : 0) + (kc << 5);
        const int bcol = (seg == 2 ? K : 0) + (kc << 5);
        const __nv_bfloat16* Abase = Ab + acol;
        const __nv_bfloat16* Bbase = Bb + bcol;
        const uint32_t sA = sb + s * 16384;
        const uint32_t sB = sA + 8192;
#pragma unroll
        for (int i = 0; i < 2; i++) {
            int cid = tid + (i << 8);
            int r = cid >> 2, c = cid & 3;
            uint32_t soff = (uint32_t)(r << 6) + (uint32_t)((c ^ ((r >> 1) & 3)) << 4);
            int arow = bm + r;
            const char* ga = (const char*)(Abase + (size_t)(arow < M ? arow : 0) * ldab) + (c << 4);
            cp_async16(sA + soff, ga, arow < M ? 16 : 0);
            const char* gb = (const char*)(Bbase + (size_t)(bn + r) * ldab) + (c << 4);
            cp_async16(sB + soff, gb, 16);
        }
        cp_commit();
    };

    issue_loads(0, 0);

    for (int kb = 0; kb < nk; kb++) {
        const int s = kb & 1;
        if (kb + 1 < nk) issue_loads(kb + 1, s ^ 1);
        if (kb + 1 < nk) cp_wait<1>(); else cp_wait<0>();
        __syncthreads();

        const uint32_t sA = sb + s * 16384;
        const uint32_t sB = sA + 8192;
        const int lr = lane & 15;         // fragment row
        const int lk = (lane >> 4) << 4;  // 0 or 16 bytes (k half)
#pragma unroll
        for (int k16 = 0; k16 < 2; k16++) {
            const int kby = (k16 << 5) + lk;
            const int csel = kby >> 4;
            uint32_t a[2][4], bf[4][4];
#pragma unroll
            for (int mt = 0; mt < 2; mt++) {
                int r = wm * 32 + mt * 16 + lr;
                uint32_t addr = sA + (uint32_t)(r << 6) + (uint32_t)((csel ^ ((r >> 1) & 3)) << 4);
                ldmatrix_x4(a[mt], addr);
            }
#pragma unroll
            for (int p = 0; p < 4; p++) {
                int r = wn * 64 + p * 16 + lr;
                uint32_t addr = sB + (uint32_t)(r << 6) + (uint32_t)((csel ^ ((r >> 1) & 3)) << 4);
                ldmatrix_x4(bf[p], addr);
            }
#pragma unroll
            for (int mt = 0; mt < 2; mt++)
#pragma unroll
                for (int nt = 0; nt < 8; nt++) {
                    int p = nt >> 1, hi = nt & 1;
                    mma16816(d[mt][nt], a[mt], bf[p][hi], bf[p][2 + hi]);
                }
        }
        __syncthreads();
    }

    // epilogue
    const int gr = lane >> 2;
    const int gc = (lane & 3) << 1;
#pragma unroll
    for (int mt = 0; mt < 2; mt++) {
        int r0 = bm + wm * 32 + mt * 16 + gr;
#pragma unroll
        for (int nt = 0; nt < 8; nt++) {
            int cc = bn + wn * 64 + nt * 8 + gc;
            if (r0 < M)
                *(float2*)(C + (size_t)r0 * Nc + cc) = make_float2(d[mt][nt][0], d[mt][nt][1]);
            if (r0 + 8 < M)
                *(float2*)(C + (size_t)(r0 + 8) * Nc + cc) = make_float2(d[mt][nt][2], d[mt][nt][3]);
        }
    }
}

// ---------------- GRU pointwise cell (writes h fp32 + hb bf16 split) ----------------
__global__ void gru_cell_k(const float* __restrict__ gi, const float* __restrict__ gh,
                           const float* __restrict__ bih, const float* __restrict__ bhh,
                           float* __restrict__ h, __nv_bfloat16* __restrict__ hb,
                           __nv_bfloat16* __restrict__ o0b, int t) {
    int idx = blockIdx.x * blockDim.x + threadIdx.x;
    if (idx >= NN * HH) return;
    int i = idx >> 7;
    int j = idx & 127;
    size_t mg = ((size_t)i * TT + t) * G3;
    size_t hg = (size_t)i * G3;
    float ir  = gi[mg + j]          + bih[j];
    float iz  = gi[mg + HH + j]     + bih[HH + j];
    float inn = gi[mg + 2 * HH + j] + bih[2 * HH + j];
    float hr  = gh[hg + j]          + bhh[j];
    float hz  = gh[hg + HH + j]     + bhh[HH + j];
    float hn  = gh[hg + 2 * HH + j] + bhh[2 * HH + j];
    float r = 1.f / (1.f + expf(-(ir + hr)));
    float z = 1.f / (1.f + expf(-(iz + hz)));
    float n = tanhf(inn + r * hn);
    float hold = h[idx];
    float hnew = (1.f - z) * n + z * hold;
    h[idx] = hnew;
    __nv_bfloat16 hi = __float2bfloat16(hnew);
    __nv_bfloat16 lo = __float2bfloat16(hnew - __bfloat162float(hi));
    hb[(size_t)i * 2 * HH + j]      = hi;
    hb[(size_t)i * 2 * HH + HH + j] = lo;
    if (o0b) {
        size_t ro = ((size_t)i * TT + t) * 2 * HH;
        o0b[ro + j]      = hi;
        o0b[ro + HH + j] = lo;
    }
}

// ---------------- GAT kernels ----------------
__global__ void gat_scores_k(const float* __restrict__ hlin,
                             const float* __restrict__ asrc, const float* __restrict__ adst,
                             float* __restrict__ es, float* __restrict__ ed,
                             unsigned* __restrict__ mu, int n) {
    int g = blockIdx.x * blockDim.x + threadIdx.x;
    int node = g >> 5;
    int lane = g & 31;
    if (node >= n) return;
    float4 h4 = reinterpret_cast<const float4*>(hlin + (size_t)node * HH)[lane];
    float4 a4 = reinterpret_cast<const float4*>(asrc)[lane];
    float4 d4 = reinterpret_cast<const float4*>(adst)[lane];
    float s = h4.x * a4.x + h4.y * a4.y + h4.z * a4.z + h4.w * a4.w;
    float d = h4.x * d4.x + h4.y * d4.y + h4.z * d4.z + h4.w * d4.w;
#pragma unroll
    for (int o = 16; o; o >>= 1) {
        s += __shfl_xor_sync(0xffffffffu, s, o);
        d += __shfl_xor_sync(0xffffffffu, d, o);
    }
    if (lane == 0) {
        es[node] = s;
        ed[node] = d;
        mu[node] = fkey(lrelu(s + d));
    }
}

__global__ void gat_edge_max_k(const int* __restrict__ ei,
                               const float* __restrict__ es, const float* __restrict__ ed,
                               float* __restrict__ eedge, unsigned* __restrict__ mu, int E) {
    int e = blockIdx.x * blockDim.x + threadIdx.x;
    if (e >= E) return;
    int s = ei[e];
    int d = ei[E + e];
    float v = lrelu(es[s] + ed[d]);
    eedge[e] = v;
    atomicMax(&mu[d], fkey(v));
}

__global__ void gat_node_init_k(const float* __restrict__ hlin,
                                const float* __restrict__ es, const float* __restrict__ ed,
                                const unsigned* __restrict__ mu,
                                float* __restrict__ m, float* __restrict__ den,
                                float* __restrict__ acc) {
    int i = blockIdx.x;
    int j = threadIdx.x;
    float mv = funkey(mu[i]);
    float w0 = expf(lrelu(es[i] + ed[i]) - mv);
    if (j == 0) { m[i] = mv; den[i] = w0; }
    acc[(size_t)i * HH + j] = w0 * hlin[(size_t)i * HH + j];
}

__global__ void gat_edge_agg_k(const int* __restrict__ ei, const float* __restrict__ eedge,
                               const float* __restrict__ m, const float* __restrict__ hlin,
                               float* __restrict__ den, float* __restrict__ acc, int E) {
    int g = blockIdx.x * blockDim.x + threadIdx.x;
    int e = g >> 5;
    int lane = g & 31;
    if (e >= E) return;
    int s = ei[e];
    int d = ei[E + e];
    float w = expf(eedge[e] - m[d]);
    if (lane == 0) atomicAdd(&den[d], w);
    float4 hv = reinterpret_cast<const float4*>(hlin + (size_t)s * HH)[lane];
    float* ap = acc + (size_t)d * HH + 4 * lane;
    atomicAdd(ap + 0, w * hv.x);
    atomicAdd(ap + 1, w * hv.y);
    atomicAdd(ap + 2, w * hv.z);
    atomicAdd(ap + 3, w * hv.w);
}

__global__ void gat_finalize_k(float* __restrict__ acc, const float* __restrict__ den,
                               const float* __restrict__ bias) {
    int i = blockIdx.x;
    int j = threadIdx.x;
    acc[(size_t)i * HH + j] = acc[(size_t)i * HH + j] / den[i] + bias[j];
}

// ---------------- sector max pool ----------------
__global__ void pool_max_k(const float* __restrict__ x, const int* __restrict__ sid,
                           unsigned* __restrict__ pu) {
    int idx = blockIdx.x * blockDim.x + threadIdx.x;
    if (idx >= NN * HH) return;
    int i = idx >> 7;
    int j = idx & 127;
    atomicMax(&pu[sid[i] * HH + j], fkey(x[idx]));
}
__global__ void pool_conv_k(const unsigned* __restrict__ pu, float* __restrict__ p,
                            __nv_bfloat16* __restrict__ pb) {
    int idx = blockIdx.x * blockDim.x + threadIdx.x;
    if (idx >= SS * HH) return;
    int r = idx >> 7, j = idx & 127;
    float v = funkey(pu[idx]);
    p[idx] = v;
    __nv_bfloat16 hi = __float2bfloat16(v);
    __nv_bfloat16 lo = __float2bfloat16(v - __bfloat162float(hi));
    pb[(size_t)r * 2 * HH + j]      = hi;
    pb[(size_t)r * 2 * HH + HH + j] = lo;
}

// ---------------- fusion head ----------------
__global__ void fusion_k(const float* __restrict__ seq, const float* __restrict__ intra,
                         const float* __restrict__ inter, const int* __restrict__ sid,
                         const float* __restrict__ fw, const float* __restrict__ fb,
                         float* __restrict__ out) {
    int g = blockIdx.x * blockDim.x + threadIdx.x;
    int i = g >> 5;
    int lane = g & 31;
    if (i >= NN) return;
    int sc = sid[i];
    const float4* s4 = reinterpret_cast<const float4*>(seq + (size_t)i * HH);
    const float4* i4 = reinterpret_cast<const float4*>(intra + (size_t)i * HH);
    const float4* e4 = reinterpret_cast<const float4*>(inter + (size_t)sc * HH);
    const float4* w4 = reinterpret_cast<const float4*>(fw);
    float sum = 0.f;
    float4 a, b;
    a = s4[lane]; b = w4[lane];
    sum += a.x * b.x + a.y * b.y + a.z * b.z + a.w * b.w;
    a = i4[lane]; b = w4[32 + lane];
    sum += a.x * b.x + a.y * b.y + a.z * b.z + a.w * b.w;
    a = e4[lane]; b = w4[64 + lane];
    sum += a.x * b.x + a.y * b.y + a.z * b.z + a.w * b.w;
#pragma unroll
    for (int o = 16; o; o >>= 1) sum += __shfl_xor_sync(0xffffffffu, sum, o);
    if (lane == 0) out[i] = sum + fb[0];
}

// ---------------- host ----------------
static inline void launch_gemm(const __nv_bfloat16* Ab, const __nv_bfloat16* Bb,
                               float* C, int M, int Nc, int K) {
    dim3 grid(Nc / 128, (M + 127) / 128);
    gemm_mma_k<<<grid, 256>>>(Ab, Bb, C, M, Nc, K);
}

extern "C" void kernel_launch(void* const* d_in, const int* in_sizes, int n_in,
                              void* d_out, int out_size) {
    const float* x        = (const float*)d_in[0];
    const int*   ei_intra = (const int*)d_in[1];
    const int*   ei_inter = (const int*)d_in[2];
    const int*   sid      = (const int*)d_in[3];
    const float* w_ih0 = (const float*)d_in[4];
    const float* w_hh0 = (const float*)d_in[5];
    const float* b_ih0 = (const float*)d_in[6];
    const float* b_hh0 = (const float*)d_in[7];
    const float* w_ih1 = (const float*)d_in[8];
    const float* w_hh1 = (const float*)d_in[9];
    const float* b_ih1 = (const float*)d_in[10];
    const float* b_hh1 = (const float*)d_in[11];
    const float* intra_W  = (const float*)d_in[12];
    const float* a_src_i  = (const float*)d_in[13];
    const float* a_dst_i  = (const float*)d_in[14];
    const float* bias_i   = (const float*)d_in[15];
    const float* inter_W  = (const float*)d_in[16];
    const float* a_src_e  = (const float*)d_in[17];
    const float* a_dst_e  = (const float*)d_in[18];
    const float* bias_e   = (const float*)d_in[19];
    const float* fw       = (const float*)d_in[20];
    const float* fb       = (const float*)d_in[21];
    float* out = (float*)d_out;

    float *gi, *gh, *h, *hlin, *acc, *es, *ed, *m, *den, *eedge, *pool, *shlin, *sacc;
    __nv_bfloat16 *xb, *o0b, *hb, *wb_ih0, *wb_hh0, *wb_ih1, *wb_hh1, *wb_a, *wb_e, *poolb;
    unsigned *mu, *pu;
    cudaGetSymbolAddress((void**)&gi, g_gi);
    cudaGetSymbolAddress((void**)&xb, g_xb);
    cudaGetSymbolAddress((void**)&o0b, g_o0b);
    cudaGetSymbolAddress((void**)&gh, g_gh);
    cudaGetSymbolAddress((void**)&h, g_h);
    cudaGetSymbolAddress((void**)&hb, g_hb);
    cudaGetSymbolAddress((void**)&hlin, g_hlin);
    cudaGetSymbolAddress((void**)&acc, g_acc);
    cudaGetSymbolAddress((void**)&wb_ih0, g_wb_ih0);
    cudaGetSymbolAddress((void**)&wb_hh0, g_wb_hh0);
    cudaGetSymbolAddress((void**)&wb_ih1, g_wb_ih1);
    cudaGetSymbolAddress((void**)&wb_hh1, g_wb_hh1);
    cudaGetSymbolAddress((void**)&wb_a, g_wb_intra);
    cudaGetSymbolAddress((void**)&wb_e, g_wb_inter);
    cudaGetSymbolAddress((void**)&es, g_es);
    cudaGetSymbolAddress((void**)&ed, g_ed);
    cudaGetSymbolAddress((void**)&m, g_m);
    cudaGetSymbolAddress((void**)&den, g_den);
    cudaGetSymbolAddress((void**)&mu, g_mu);
    cudaGetSymbolAddress((void**)&eedge, g_eedge);
    cudaGetSymbolAddress((void**)&pu, g_pu);
    cudaGetSymbolAddress((void**)&pool, g_pool);
    cudaGetSymbolAddress((void**)&poolb, g_poolb);
    cudaGetSymbolAddress((void**)&shlin, g_shlin);
    cudaGetSymbolAddress((void**)&sacc, g_sacc);

    const int cellGrid = (NN * HH + 255) / 256;

    // ---- GRU layer 0 ----
    convw_k<<<(G3 * INP + 255) / 256, 256>>>(w_ih0, wb_ih0, G3, INP);
    convw_k<<<(NN * TT * INP + 255) / 256, 256>>>(x, xb, NN * TT, INP);
    launch_gemm(xb, wb_ih0, gi, NN * TT, G3, INP);
    convw_k<<<(G3 * HH + 255) / 256, 256>>>(w_hh0, wb_hh0, G3, HH);
    zerof_k<<<(NN * HH + 255) / 256, 256>>>(h, NN * HH);
    zerou_k<<<(NN * HH + 255) / 256, 256>>>((unsigned*)hb, NN * HH);
    for (int t = 0; t < TT; t++) {
        launch_gemm(hb, wb_hh0, gh, NN, G3, HH);
        gru_cell_k<<<cellGrid, 256>>>(gi, gh, b_ih0, b_hh0, h, hb, o0b, t);
    }

    // ---- GRU layer 1 ----
    convw_k<<<(G3 * HH + 255) / 256, 256>>>(w_ih1, wb_ih1, G3, HH);
    launch_gemm(o0b, wb_ih1, gi, NN * TT, G3, HH);
    convw_k<<<(G3 * HH + 255) / 256, 256>>>(w_hh1, wb_hh1, G3, HH);
    zerof_k<<<(NN * HH + 255) / 256, 256>>>(h, NN * HH);
    zerou_k<<<(NN * HH + 255) / 256, 256>>>((unsigned*)hb, NN * HH);
    for (int t = 0; t < TT; t++) {
        launch_gemm(hb, wb_hh1, gh, NN, G3, HH);
        gru_cell_k<<<cellGrid, 256>>>(gi, gh, b_ih1, b_hh1, h, hb, nullptr, t);
    }
    // h == seq_emb (fp32), hb == its bf16 split

    // ---- intra GAT ----
    convw_k<<<(HH * HH + 255) / 256, 256>>>(intra_W, wb_a, HH, HH);
    launch_gemm(hb, wb_a, hlin, NN, HH, HH);
    gat_scores_k<<<(NN * 32 + 255) / 256, 256>>>(hlin, a_src_i, a_dst_i, es, ed, mu, NN);
    gat_edge_max_k<<<(EINTRA + 255) / 256, 256>>>(ei_intra, es, ed, eedge, mu, EINTRA);
    gat_node_init_k<<<NN, HH>>>(hlin, es, ed, mu, m, den, acc);
    gat_edge_agg_k<<<(EINTRA * 32 + 255) / 256, 256>>>(ei_intra, eedge, m, hlin, den, acc, EINTRA);
    gat_finalize_k<<<NN, HH>>>(acc, den, bias_i);
    // acc == intra_emb

    // ---- sector max pool ----
    zerou_k<<<(SS * HH + 255) / 256, 256>>>(pu, SS * HH);
    pool_max_k<<<(NN * HH + 255) / 256, 256>>>(acc, sid, pu);
    pool_conv_k<<<(SS * HH + 255) / 256, 256>>>(pu, pool, poolb);

    // ---- inter GAT (S=64) ----
    convw_k<<<(HH * HH + 255) / 256, 256>>>(inter_W, wb_e, HH, HH);
    launch_gemm(poolb, wb_e, shlin, SS, HH, HH);
    gat_scores_k<<<(SS * 32 + 255) / 256, 256>>>(shlin, a_src_e, a_dst_e, es, ed, mu, SS);
    gat_edge_max_k<<<(EINTER + 255) / 256, 256>>>(ei_inter, es, ed, eedge, mu, EINTER);
    gat_node_init_k<<<SS, HH>>>(shlin, es, ed, mu, m, den, sacc);
    gat_edge_agg_k<<<(EINTER * 32 + 255) / 256, 256>>>(ei_inter, eedge, m, shlin, den, sacc, EINTER);
    gat_finalize_k<<<SS, HH>>>(sacc, den, bias_e);
    // sacc == inter_sec

    // ---- fusion ----
    fusion_k<<<(NN * 32 + 255) / 256, 256>>>(h, acc, sacc, sid, fw, fb, out);
}